// round 2
// baseline (speedup 1.0000x reference)
#include <cuda_runtime.h>
#include <cstdint>

#define BDIM   32
#define SDIM   2048
#define HDIM   512
#define DHDIM  2048
#define MTOK   65536

#define BM 64
#define BN 128
#define BK 32
#define NCHUNK 4
#define KITERS 16

#define AS_STRIDE 516   // 512 + 4 pad (conflict-free frag loads)
#define BS_STRIDE 132   // 128 + 4 pad

// smem layout (floats)
#define AS_FLOATS   (64 * AS_STRIDE)             // 33024
#define BS_FLOATS   (2 * 32 * BS_STRIDE)         // 8448
#define HPS_FLOATS  (32 * 128)                   // 4096
#define VS_FLOATS   (128)
#define RED_FLOATS  (4 * 64)
#define SMEM_FLOATS (AS_FLOATS + BS_FLOATS + HPS_FLOATS + VS_FLOATS + RED_FLOATS)
#define SMEM_BYTES  (SMEM_FLOATS * 4)

__device__ float g_hp[BDIM * HDIM];   // h_part + bias, fp32 exact

// ---------------------------------------------------------------------------
// helpers
// ---------------------------------------------------------------------------
__device__ __forceinline__ uint32_t f2tf32(float x) {
    uint32_t r;
    asm("cvt.rna.tf32.f32 %0, %1;" : "=r"(r) : "f"(x));
    return r;
}

__device__ __forceinline__ float tanh_fast(float x) {
    // 1 - 2/(e^{2x}+1); |x| bounded by ~1 here (tanh input), rel err ~1e-6
    float e = __expf(2.0f * x);
    return 1.0f - __fdividef(2.0f, e + 1.0f);
}

__device__ __forceinline__ void mma8(float& c0, float& c1, float& c2, float& c3,
                                     uint32_t a0, uint32_t a1, uint32_t a2, uint32_t a3,
                                     uint32_t b0, uint32_t b1) {
    asm volatile(
        "mma.sync.aligned.m16n8k8.row.col.f32.tf32.tf32.f32 "
        "{%0,%1,%2,%3}, {%4,%5,%6,%7}, {%8,%9}, {%0,%1,%2,%3};"
        : "+f"(c0), "+f"(c1), "+f"(c2), "+f"(c3)
        : "r"(a0), "r"(a1), "r"(a2), "r"(a3), "r"(b0), "r"(b1));
}

// ---------------------------------------------------------------------------
// Kernel 1: h_part[b][d] = hidden[b,:] @ W_h[:,d] + b_attn[d]   (fp32 exact)
// grid (8, 4): blockIdx.x = b-group of 4, blockIdx.y = d-chunk of 128
// ---------------------------------------------------------------------------
__global__ void __launch_bounds__(256) hp_kernel(
    const float* __restrict__ hidden,
    const float* __restrict__ W_attn,
    const float* __restrict__ b_attn)
{
    __shared__ float hid_s[4 * DHDIM];   // 32 KB
    __shared__ float red[256 * 4];       // 4 KB

    int bg  = blockIdx.x;   // 0..7
    int dc  = blockIdx.y;   // 0..3
    int tid = threadIdx.x;

    // load 4 hidden rows
    const float4* hsrc = reinterpret_cast<const float4*>(hidden + bg * 4 * DHDIM);
    float4*       hdst = reinterpret_cast<float4*>(hid_s);
    for (int i = tid; i < (4 * DHDIM) / 4; i += 256) hdst[i] = hsrc[i];
    __syncthreads();

    int d_l  = tid & 127;
    int half = tid >> 7;        // 0 or 1 (h split)
    int d    = dc * 128 + d_l;

    float a0 = 0.f, a1 = 0.f, a2 = 0.f, a3 = 0.f;
    const float* wp = W_attn + (size_t)(half * 1024) * HDIM + d;
    int hbase = half * 1024;
#pragma unroll 4
    for (int h = 0; h < 1024; ++h) {
        float w = wp[0];
        wp += HDIM;
        int hh = hbase + h;
        a0 += hid_s[0 * DHDIM + hh] * w;
        a1 += hid_s[1 * DHDIM + hh] * w;
        a2 += hid_s[2 * DHDIM + hh] * w;
        a3 += hid_s[3 * DHDIM + hh] * w;
    }
    red[tid * 4 + 0] = a0;
    red[tid * 4 + 1] = a1;
    red[tid * 4 + 2] = a2;
    red[tid * 4 + 3] = a3;
    __syncthreads();

    if (tid < 128) {
        int dd = dc * 128 + tid;
        float bias = b_attn[dd];
#pragma unroll
        for (int q = 0; q < 4; ++q) {
            float s = red[tid * 4 + q] + red[(tid + 128) * 4 + q] + bias;
            g_hp[(bg * 4 + q) * HDIM + dd] = s;
        }
    }
}

// ---------------------------------------------------------------------------
// Kernel 2: fused GEMM (tf32 mma.sync) + tanh + v-dot -> logits into d_out
// grid: 1024 blocks (64 tokens each), 256 threads (8 warps, 2x4)
// ---------------------------------------------------------------------------
__device__ __forceinline__ void ldgB(const float* __restrict__ Wg, int kt,
                                     float4 br[4], int tid)
{
#pragma unroll
    for (int q = 0; q < 4; ++q) {
        int idx = q * 256 + tid;
        int row = idx >> 5;          // 0..31
        int c4  = idx & 31;          // 0..31 (float4 within 128 cols)
        br[q] = *reinterpret_cast<const float4*>(Wg + (size_t)(kt * BK + row) * HDIM + c4 * 4);
    }
}

__device__ __forceinline__ void stsB(float* __restrict__ bs, const float4 br[4], int tid)
{
#pragma unroll
    for (int q = 0; q < 4; ++q) {
        int idx = q * 256 + tid;
        int row = idx >> 5;
        int c4  = idx & 31;
        float4 t;
        t.x = __uint_as_float(f2tf32(br[q].x));
        t.y = __uint_as_float(f2tf32(br[q].y));
        t.z = __uint_as_float(f2tf32(br[q].z));
        t.w = __uint_as_float(f2tf32(br[q].w));
        *reinterpret_cast<float4*>(bs + row * BS_STRIDE + c4 * 4) = t;
    }
}

__global__ void __launch_bounds__(256) main_kernel(
    const float* __restrict__ enc,
    const float* __restrict__ W_attn,
    const float* __restrict__ v,
    float* __restrict__ out)
{
    extern __shared__ float smem[];
    float* As  = smem;                           // [64][516]
    float* Bs  = As + AS_FLOATS;                 // [2][32][132]
    float* hps = Bs + BS_FLOATS;                 // [32][128]
    float* vs  = hps + HPS_FLOATS;               // [128]
    float* red = vs + VS_FLOATS;                 // [4][64]

    int tid  = threadIdx.x;
    int lane = tid & 31;
    int warp = tid >> 5;
    int wm   = warp >> 2;      // 0..1
    int wn   = warp & 3;       // 0..3
    int grp  = lane >> 2;      // groupID 0..7
    int tig  = lane & 3;       // 0..3

    // ---- load A tile (64 x 512) once, converted to tf32 ----
    const float* Ag = enc + (size_t)blockIdx.x * BM * HDIM;
    for (int i = tid; i < (BM * HDIM) / 4; i += 256) {
        float4 a = reinterpret_cast<const float4*>(Ag)[i];
        int row = i >> 7;          // 128 float4 per row
        int c4  = i & 127;
        float4 t;
        t.x = __uint_as_float(f2tf32(a.x));
        t.y = __uint_as_float(f2tf32(a.y));
        t.z = __uint_as_float(f2tf32(a.z));
        t.w = __uint_as_float(f2tf32(a.w));
        *reinterpret_cast<float4*>(As + row * AS_STRIDE + c4 * 4) = t;
    }

    const float* We = W_attn + (size_t)DHDIM * HDIM;   // W_e base
    float lp[4] = {0.f, 0.f, 0.f, 0.f};

    for (int nc = 0; nc < NCHUNK; ++nc) {
        float c[2][4][4];
#pragma unroll
        for (int mi = 0; mi < 2; ++mi)
#pragma unroll
            for (int ni = 0; ni < 4; ++ni)
#pragma unroll
                for (int q = 0; q < 4; ++q) c[mi][ni][q] = 0.f;

        float4 br[4];
        ldgB(We + nc * BN, 0, br, tid);

        __syncthreads();   // previous chunk fully done (epilogue reads of hps/vs, Bs reads)

        // stage hp chunk + v chunk
        for (int i = tid; i < 32 * 128; i += 256)
            hps[i] = g_hp[(i >> 7) * HDIM + nc * 128 + (i & 127)];
        if (tid < 128) vs[tid] = v[nc * 128 + tid];

        stsB(Bs, br, tid);   // stage 0
        int stage = 0;

        for (int kt = 0; kt < KITERS; ++kt) {
            __syncthreads();   // stage data + (kt==0) hps/vs visible; prior-stage reads done
            if (kt < KITERS - 1) ldgB(We + nc * BN, kt + 1, br, tid);

            const float* bsp = Bs + stage * (32 * BS_STRIDE);
#pragma unroll
            for (int ks = 0; ks < 4; ++ks) {
                int kc = kt * BK + ks * 8 + tig;
                uint32_t a[2][4];
#pragma unroll
                for (int mi = 0; mi < 2; ++mi) {
                    const float* ap = As + (wm * 32 + mi * 16 + grp) * AS_STRIDE + kc;
                    a[mi][0] = __float_as_uint(ap[0]);
                    a[mi][1] = __float_as_uint(ap[8 * AS_STRIDE]);
                    a[mi][2] = __float_as_uint(ap[4]);
                    a[mi][3] = __float_as_uint(ap[8 * AS_STRIDE + 4]);
                }
#pragma unroll
                for (int ni = 0; ni < 4; ++ni) {
                    const float* bp = bsp + (ks * 8 + tig) * BS_STRIDE + wn * 32 + ni * 8 + grp;
                    uint32_t b0 = __float_as_uint(bp[0]);
                    uint32_t b1 = __float_as_uint(bp[4 * BS_STRIDE]);
                    mma8(c[0][ni][0], c[0][ni][1], c[0][ni][2], c[0][ni][3],
                         a[0][0], a[0][1], a[0][2], a[0][3], b0, b1);
                    mma8(c[1][ni][0], c[1][ni][1], c[1][ni][2], c[1][ni][3],
                         a[1][0], a[1][1], a[1][2], a[1][3], b0, b1);
                }
            }
            if (kt < KITERS - 1) {
                stsB(Bs + (stage ^ 1) * (32 * BS_STRIDE), br, tid);
                stage ^= 1;
            }
        }

        // ---- epilogue: lp += tanh(c + hp) * v ----
#pragma unroll
        for (int mi = 0; mi < 2; ++mi) {
#pragma unroll
            for (int ni = 0; ni < 4; ++ni) {
                int n0 = wn * 32 + ni * 8 + 2 * tig;
                float v0 = vs[n0], v1 = vs[n0 + 1];
                int r0 = wm * 32 + mi * 16 + grp;
                int b0 = r0 & 31;
                int b1 = (r0 + 8) & 31;
                float hp00 = hps[b0 * 128 + n0], hp01 = hps[b0 * 128 + n0 + 1];
                float hp10 = hps[b1 * 128 + n0], hp11 = hps[b1 * 128 + n0 + 1];
                lp[mi * 2 + 0] += tanh_fast(c[mi][ni][0] + hp00) * v0
                                + tanh_fast(c[mi][ni][1] + hp01) * v1;
                lp[mi * 2 + 1] += tanh_fast(c[mi][ni][2] + hp10) * v0
                                + tanh_fast(c[mi][ni][3] + hp11) * v1;
            }
        }
    }

    // ---- deterministic reduction: lanes (tig) -> warp_n -> rows ----
#pragma unroll
    for (int j = 0; j < 4; ++j) {
        lp[j] += __shfl_xor_sync(0xffffffffu, lp[j], 1);
        lp[j] += __shfl_xor_sync(0xffffffffu, lp[j], 2);
    }
    __syncthreads();   // all k-loop / epilogue smem traffic done before red reuse
    if (tig == 0) {
#pragma unroll
        for (int j = 0; j < 4; ++j) {
            int row = wm * 32 + (j >> 1) * 16 + grp + (j & 1) * 8;
            red[wn * 64 + row] = lp[j];
        }
    }
    __syncthreads();
    if (tid < 64) {
        float lg = red[tid] + red[64 + tid] + red[128 + tid] + red[192 + tid];
        int f = blockIdx.x * BM + tid;
        out[(f & 31) * SDIM + (f >> 5)] = lg;   // logits laid out (b, s)
    }
}

// ---------------------------------------------------------------------------
// Kernel 3: softmax over s (2048) per batch row, in place on d_out
// ---------------------------------------------------------------------------
__global__ void __launch_bounds__(256) softmax_kernel(float* __restrict__ out)
{
    __shared__ float sred[8];
    int b   = blockIdx.x;
    int tid = threadIdx.x;
    float* row = out + (size_t)b * SDIM;

    float vals[8];
    float mx = -3.4e38f;
#pragma unroll
    for (int i = 0; i < 8; ++i) {
        vals[i] = row[tid + i * 256];
        mx = fmaxf(mx, vals[i]);
    }
#pragma unroll
    for (int o = 16; o > 0; o >>= 1) mx = fmaxf(mx, __shfl_xor_sync(0xffffffffu, mx, o));
    if ((tid & 31) == 0) sred[tid >> 5] = mx;
    __syncthreads();
    mx = sred[0];
#pragma unroll
    for (int w = 1; w < 8; ++w) mx = fmaxf(mx, sred[w]);
    __syncthreads();   // before reusing sred for sum

    float sum = 0.f;
#pragma unroll
    for (int i = 0; i < 8; ++i) {
        vals[i] = __expf(vals[i] - mx);
        sum += vals[i];
    }
#pragma unroll
    for (int o = 16; o > 0; o >>= 1) sum += __shfl_xor_sync(0xffffffffu, sum, o);
    if ((tid & 31) == 0) sred[tid >> 5] = sum;
    __syncthreads();
    float tot = 0.f;
#pragma unroll
    for (int w = 0; w < 8; ++w) tot += sred[w];
    float inv = 1.0f / tot;
#pragma unroll
    for (int i = 0; i < 8; ++i) row[tid + i * 256] = vals[i] * inv;
}

// ---------------------------------------------------------------------------
extern "C" void kernel_launch(void* const* d_in, const int* in_sizes, int n_in,
                              void* d_out, int out_size)
{
    const float* hidden = (const float*)d_in[0];
    const float* enc    = (const float*)d_in[1];
    const float* W_attn = (const float*)d_in[2];
    const float* b_attn = (const float*)d_in[3];
    const float* v      = (const float*)d_in[4];
    float* out = (float*)d_out;

    (void)in_sizes; (void)n_in; (void)out_size;

    static cudaError_t attr_rc = cudaFuncSetAttribute(
        main_kernel, cudaFuncAttributeMaxDynamicSharedMemorySize, SMEM_BYTES);
    (void)attr_rc;

    hp_kernel<<<dim3(8, 4), 256>>>(hidden, W_attn, b_attn);
    main_kernel<<<MTOK / BM, 256, SMEM_BYTES>>>(enc, W_attn, v, out);
    softmax_kernel<<<BDIM, 256>>>(out);
}

// round 3
// speedup vs baseline: 1.3647x; 1.3647x over previous
#include <cuda_runtime.h>
#include <cstdint>

#define BDIM   32
#define SDIM   2048
#define HDIM   512
#define DHDIM  2048
#define MTOK   65536

#define BM 64
#define BN 128
#define BK 32
#define NCHUNK 4
#define GCHUNKS 64          // 4 nc * 16 kt

#define AS_STRIDE 516       // 512 + 4 pad
#define BS_STRIDE 132       // 128 + 4 pad
#define HPS_STRIDE 132

#define BSTAGE_FLOATS (32 * BS_STRIDE)           // one B stage
#define AS_FLOATS   (64 * AS_STRIDE)             // 33024
#define BS_FLOATS   (3 * BSTAGE_FLOATS)          // 12672 (3-stage ring)
#define HPS_FLOATS  (32 * HPS_STRIDE)            // 4224
#define VS_FLOATS   (128)
#define RED_FLOATS  (4 * 64)
#define SMEM_FLOATS (AS_FLOATS + BS_FLOATS + HPS_FLOATS + VS_FLOATS + RED_FLOATS)
#define SMEM_BYTES  (SMEM_FLOATS * 4)            // ~196.6 KB

__device__ float g_hp[BDIM * HDIM];              // h_part + bias, fp32
__device__ float g_hp_part[16 * BDIM * HDIM];    // split-K partials

// ---------------------------------------------------------------------------
// helpers
// ---------------------------------------------------------------------------
__device__ __forceinline__ void cp16(void* dst_smem, const void* src) {
    uint32_t d = (uint32_t)__cvta_generic_to_shared(dst_smem);
    asm volatile("cp.async.ca.shared.global [%0], [%1], 16;\n" :: "r"(d), "l"(src));
}
__device__ __forceinline__ void cp_commit() {
    asm volatile("cp.async.commit_group;\n");
}
template<int N>
__device__ __forceinline__ void cp_wait() {
    asm volatile("cp.async.wait_group %0;\n" :: "n"(N));
}

__device__ __forceinline__ float tanh_fast(float x) {
    float e = __expf(2.0f * x);
    return 1.0f - __fdividef(2.0f, e + 1.0f);
}

__device__ __forceinline__ void mma8(float& c0, float& c1, float& c2, float& c3,
                                     uint32_t a0, uint32_t a1, uint32_t a2, uint32_t a3,
                                     uint32_t b0, uint32_t b1) {
    asm volatile(
        "mma.sync.aligned.m16n8k8.row.col.f32.tf32.tf32.f32 "
        "{%0,%1,%2,%3}, {%4,%5,%6,%7}, {%8,%9}, {%0,%1,%2,%3};"
        : "+f"(c0), "+f"(c1), "+f"(c2), "+f"(c3)
        : "r"(a0), "r"(a1), "r"(a2), "r"(a3), "r"(b0), "r"(b1));
}

// ---------------------------------------------------------------------------
// hp1: split-K partials.  part[ks][b][d] = sum_{k in ks-chunk} hidden[b][k]*W_h[k][d]
// grid (32 b, 16 ks, 2 dz), 256 threads: thread owns one (b, d), 128-k chunk
// ---------------------------------------------------------------------------
__global__ void __launch_bounds__(256) hp1_kernel(
    const float* __restrict__ hidden,
    const float* __restrict__ W_attn)
{
    int b  = blockIdx.x;
    int ks = blockIdx.y;
    int d  = blockIdx.z * 256 + threadIdx.x;

    const float* hrow = hidden + (size_t)b * DHDIM + ks * 128;
    const float* wp   = W_attn + (size_t)(ks * 128) * HDIM + d;

    float acc = 0.f;
#pragma unroll 8
    for (int k = 0; k < 128; ++k)
        acc += __ldg(hrow + k) * wp[(size_t)k * HDIM];

    g_hp_part[((size_t)ks * BDIM + b) * HDIM + d] = acc;
}

// hp2: reduce 16 partials + bias -> g_hp.  16384 threads.
__global__ void __launch_bounds__(256) hp2_kernel(const float* __restrict__ b_attn)
{
    int i = blockIdx.x * 256 + threadIdx.x;   // (b*512 + d)
    int d = i & (HDIM - 1);
    float s = b_attn[d];
#pragma unroll
    for (int ks = 0; ks < 16; ++ks)
        s += g_hp_part[(size_t)ks * (BDIM * HDIM) + i];
    g_hp[i] = s;
}

// ---------------------------------------------------------------------------
// main: fused GEMM (tf32 mma.sync, cp.async 3-stage) + tanh + v-dot -> logits
// grid: 1024 blocks (64 tokens), 256 threads (8 warps, 2x4)
// ---------------------------------------------------------------------------
__device__ __forceinline__ void cpB(float* __restrict__ bs,
                                    const float* __restrict__ We,
                                    int g, int tid)
{
    int nc = g >> 4, kt = g & 15;
    const float* src = We + (size_t)(kt * BK) * HDIM + nc * BN;
#pragma unroll
    for (int q = 0; q < 4; ++q) {
        int idx = q * 256 + tid;
        int row = idx >> 5;          // 0..31
        int c4  = idx & 31;          // float4 within 128 cols
        cp16(bs + row * BS_STRIDE + c4 * 4, src + (size_t)row * HDIM + c4 * 4);
    }
}

__global__ void __launch_bounds__(256) main_kernel(
    const float* __restrict__ enc,
    const float* __restrict__ W_attn,
    const float* __restrict__ v,
    float* __restrict__ out)
{
    extern __shared__ float smem[];
    float* As  = smem;                           // [64][516]  raw fp32 (HW-truncated tf32)
    float* Bs  = As + AS_FLOATS;                 // [3][32][132]
    float* hps = Bs + BS_FLOATS;                 // [32][132]
    float* vs  = hps + HPS_FLOATS;               // [128]
    float* red = vs + VS_FLOATS;                 // [4][64]

    int tid  = threadIdx.x;
    int lane = tid & 31;
    int warp = tid >> 5;
    int wm   = warp >> 2;      // 0..1
    int wn   = warp & 3;       // 0..3
    int grp  = lane >> 2;      // 0..7
    int tig  = lane & 3;       // 0..3

    const float* We = W_attn + (size_t)DHDIM * HDIM;

    // ---- group 0: whole A tile (64x512) + B chunk 0;  group 1: B chunk 1 ----
    const float* Ag = enc + (size_t)blockIdx.x * BM * HDIM;
#pragma unroll 4
    for (int i = tid; i < BM * 128; i += 256) {   // 16B chunks
        int row = i >> 7;
        int c4  = i & 127;
        cp16(As + row * AS_STRIDE + c4 * 4, Ag + (size_t)row * HDIM + c4 * 4);
    }
    cpB(Bs, We, 0, tid);
    cp_commit();                                  // G0
    cpB(Bs + BSTAGE_FLOATS, We, 1, tid);
    cp_commit();                                  // G1

    float lp[4] = {0.f, 0.f, 0.f, 0.f};
    float c[2][4][4];

    for (int g = 0; g < GCHUNKS; ++g) {
        int kt = g & 15;
        int nc = g >> 4;

        if (kt == 0) {
            __syncthreads();   // previous epilogue done reading hps/vs
            for (int i = tid; i < 32 * 128; i += 256)
                hps[(i >> 7) * HPS_STRIDE + (i & 127)] =
                    g_hp[(i >> 7) * HDIM + nc * 128 + (i & 127)];
            if (tid < 128) vs[tid] = v[nc * 128 + tid];
#pragma unroll
            for (int mi = 0; mi < 2; ++mi)
#pragma unroll
                for (int ni = 0; ni < 4; ++ni)
#pragma unroll
                    for (int q = 0; q < 4; ++q) c[mi][ni][q] = 0.f;
        }

        cp_wait<1>();          // stage g landed (2 groups pending -> drain to 1)
        __syncthreads();       // visible to all warps; stage g-1 fully consumed

        const float* bsp = Bs + (g % 3) * BSTAGE_FLOATS;
#pragma unroll
        for (int ks = 0; ks < 4; ++ks) {
            int kc = kt * BK + ks * 8 + tig;
            uint32_t a[2][4];
#pragma unroll
            for (int mi = 0; mi < 2; ++mi) {
                const float* ap = As + (wm * 32 + mi * 16 + grp) * AS_STRIDE + kc;
                a[mi][0] = __float_as_uint(ap[0]);
                a[mi][1] = __float_as_uint(ap[8 * AS_STRIDE]);
                a[mi][2] = __float_as_uint(ap[4]);
                a[mi][3] = __float_as_uint(ap[8 * AS_STRIDE + 4]);
            }
#pragma unroll
            for (int ni = 0; ni < 4; ++ni) {
                const float* bp = bsp + (ks * 8 + tig) * BS_STRIDE + wn * 32 + ni * 8 + grp;
                uint32_t b0 = __float_as_uint(bp[0]);
                uint32_t b1 = __float_as_uint(bp[4 * BS_STRIDE]);
                mma8(c[0][ni][0], c[0][ni][1], c[0][ni][2], c[0][ni][3],
                     a[0][0], a[0][1], a[0][2], a[0][3], b0, b1);
                mma8(c[1][ni][0], c[1][ni][1], c[1][ni][2], c[1][ni][3],
                     a[1][0], a[1][1], a[1][2], a[1][3], b0, b1);
            }
        }

        if (g + 2 < GCHUNKS) cpB(Bs + ((g + 2) % 3) * BSTAGE_FLOATS, We, g + 2, tid);
        cp_commit();           // always commit (possibly empty) to keep count fixed

        if (kt == 15) {
            // ---- epilogue: lp += tanh(c + hp) * v ----
#pragma unroll
            for (int mi = 0; mi < 2; ++mi) {
#pragma unroll
                for (int ni = 0; ni < 4; ++ni) {
                    int n0 = wn * 32 + ni * 8 + 2 * tig;
                    float v0 = vs[n0], v1 = vs[n0 + 1];
                    int r0 = wm * 32 + mi * 16 + grp;
                    int b0 = r0 & 31;
                    int b1 = (r0 + 8) & 31;
                    float hp00 = hps[b0 * HPS_STRIDE + n0], hp01 = hps[b0 * HPS_STRIDE + n0 + 1];
                    float hp10 = hps[b1 * HPS_STRIDE + n0], hp11 = hps[b1 * HPS_STRIDE + n0 + 1];
                    lp[mi * 2 + 0] += tanh_fast(c[mi][ni][0] + hp00) * v0
                                    + tanh_fast(c[mi][ni][1] + hp01) * v1;
                    lp[mi * 2 + 1] += tanh_fast(c[mi][ni][2] + hp10) * v0
                                    + tanh_fast(c[mi][ni][3] + hp11) * v1;
                }
            }
        }
    }

    // ---- deterministic reduction: lanes (tig) -> warp_n -> rows ----
#pragma unroll
    for (int j = 0; j < 4; ++j) {
        lp[j] += __shfl_xor_sync(0xffffffffu, lp[j], 1);
        lp[j] += __shfl_xor_sync(0xffffffffu, lp[j], 2);
    }
    __syncthreads();
    if (tig == 0) {
#pragma unroll
        for (int j = 0; j < 4; ++j) {
            int row = wm * 32 + (j >> 1) * 16 + grp + (j & 1) * 8;
            red[wn * 64 + row] = lp[j];
        }
    }
    __syncthreads();
    if (tid < 64) {
        float lg = red[tid] + red[64 + tid] + red[128 + tid] + red[192 + tid];
        int f = blockIdx.x * BM + tid;
        out[(f & 31) * SDIM + (f >> 5)] = lg;   // logits (b, s)
    }
}

// ---------------------------------------------------------------------------
// softmax over s (2048) per batch row, in place
// ---------------------------------------------------------------------------
__global__ void __launch_bounds__(256) softmax_kernel(float* __restrict__ out)
{
    __shared__ float sred[8];
    int b   = blockIdx.x;
    int tid = threadIdx.x;
    float* row = out + (size_t)b * SDIM;

    float vals[8];
    float mx = -3.4e38f;
#pragma unroll
    for (int i = 0; i < 8; ++i) {
        vals[i] = row[tid + i * 256];
        mx = fmaxf(mx, vals[i]);
    }
#pragma unroll
    for (int o = 16; o > 0; o >>= 1) mx = fmaxf(mx, __shfl_xor_sync(0xffffffffu, mx, o));
    if ((tid & 31) == 0) sred[tid >> 5] = mx;
    __syncthreads();
    mx = sred[0];
#pragma unroll
    for (int w = 1; w < 8; ++w) mx = fmaxf(mx, sred[w]);
    __syncthreads();

    float sum = 0.f;
#pragma unroll
    for (int i = 0; i < 8; ++i) {
        vals[i] = __expf(vals[i] - mx);
        sum += vals[i];
    }
#pragma unroll
    for (int o = 16; o > 0; o >>= 1) sum += __shfl_xor_sync(0xffffffffu, sum, o);
    if ((tid & 31) == 0) sred[tid >> 5] = sum;
    __syncthreads();
    float tot = 0.f;
#pragma unroll
    for (int w = 0; w < 8; ++w) tot += sred[w];
    float inv = 1.0f / tot;
#pragma unroll
    for (int i = 0; i < 8; ++i) row[tid + i * 256] = vals[i] * inv;
}

// ---------------------------------------------------------------------------
extern "C" void kernel_launch(void* const* d_in, const int* in_sizes, int n_in,
                              void* d_out, int out_size)
{
    const float* hidden = (const float*)d_in[0];
    const float* enc    = (const float*)d_in[1];
    const float* W_attn = (const float*)d_in[2];
    const float* b_attn = (const float*)d_in[3];
    const float* v      = (const float*)d_in[4];
    float* out = (float*)d_out;

    (void)in_sizes; (void)n_in; (void)out_size;

    static cudaError_t attr_rc = cudaFuncSetAttribute(
        main_kernel, cudaFuncAttributeMaxDynamicSharedMemorySize, SMEM_BYTES);
    (void)attr_rc;

    hp1_kernel<<<dim3(32, 16, 2), 256>>>(hidden, W_attn);
    hp2_kernel<<<64, 256>>>(b_attn);
    main_kernel<<<MTOK / BM, 256, SMEM_BYTES>>>(enc, W_attn, v, out);
    softmax_kernel<<<BDIM, 256>>>(out);
}

// round 5
// speedup vs baseline: 1.9949x; 1.4617x over previous
#include <cuda_runtime.h>
#include <cstdint>

#define BDIM   32
#define SDIM   2048
#define HDIM   512
#define DHDIM  2048
#define MTOK   65536

#define BM 128
#define BN 256          // per nt half
#define NT 2
#define BK 32
#define KT 16

// smem layout (floats)
#define VS_FLOATS    512
#define RED_FLOATS   512
#define A_FLOATS     4096          // 128 x 32, swizzled
#define B_FLOATS     8192          // 256 x 32, fragment-major
#define STAGE_FLOATS (A_FLOATS + B_FLOATS)       // 12288
#define SMEM_FLOATS  (VS_FLOATS + RED_FLOATS + 3 * STAGE_FLOATS)
#define SMEM_BYTES   (SMEM_FLOATS * 4)           // 151552
#define HPS_STRIDE   264

__device__ float g_hp[BDIM * HDIM];
__device__ float g_hp_part[16 * BDIM * HDIM];
__device__ float g_Wfrag[HDIM * HDIM];           // fragment-major W_e

// ---------------------------------------------------------------------------
// helpers
// ---------------------------------------------------------------------------
__device__ __forceinline__ void cp16(void* dst_smem, const void* src) {
    uint32_t d = (uint32_t)__cvta_generic_to_shared(dst_smem);
    asm volatile("cp.async.ca.shared.global [%0], [%1], 16;\n" :: "r"(d), "l"(src));
}
__device__ __forceinline__ void cp_commit() {
    asm volatile("cp.async.commit_group;\n");
}
template<int N>
__device__ __forceinline__ void cp_wait() {
    asm volatile("cp.async.wait_group %0;\n" :: "n"(N));
}

__device__ __forceinline__ void mma8(float* c,
                                     uint32_t a0, uint32_t a1, uint32_t a2, uint32_t a3,
                                     uint32_t b0, uint32_t b1) {
    asm volatile(
        "mma.sync.aligned.m16n8k8.row.col.f32.tf32.tf32.f32 "
        "{%0,%1,%2,%3}, {%4,%5,%6,%7}, {%8,%9}, {%0,%1,%2,%3};"
        : "+f"(c[0]), "+f"(c[1]), "+f"(c[2]), "+f"(c[3])
        : "r"(a0), "r"(a1), "r"(a2), "r"(a3), "r"(b0), "r"(b1));
}

// FFMA-only tanh: tanh(x) = 1 - 2/(e^{2x}+1), exp2 via bit tricks + poly,
// reciprocal via magic + 3 Newton iters.  abs err ~1e-5, no MUFU.
__device__ __forceinline__ float tanh_fma(float x) {
    x = fminf(fmaxf(x, -15.0f), 15.0f);
    const float L2E2 = 2.885390081777927f;       // 2*log2(e)
    float tm = fmaf(x, L2E2, 12582912.0f);       // round-to-nearest trick
    int   ei = __float_as_int(tm) - 0x4B400000;  // round(t)
    float r  = fmaf(x, L2E2, 12582912.0f - tm);  // t - round(t) in [-0.5, 0.5]
    float p  = 1.54035303934e-4f;                // 2^r Taylor deg 6 (err ~1e-7)
    p = fmaf(p, r, 1.33335581464e-3f);
    p = fmaf(p, r, 9.61812910763e-3f);
    p = fmaf(p, r, 5.55041086648e-2f);
    p = fmaf(p, r, 2.40226506959e-1f);
    p = fmaf(p, r, 6.93147180560e-1f);
    p = fmaf(p, r, 1.0f);
    float y  = p * __int_as_float((ei + 127) << 23);   // e^{2x}
    float e1 = y + 1.0f;
    float rc = __int_as_float(0x7EF127EAu - (uint32_t)__float_as_int(e1));
    rc = rc * fmaf(-e1, rc, 2.0f);
    rc = rc * fmaf(-e1, rc, 2.0f);
    rc = rc * fmaf(-e1, rc, 2.0f);
    return fmaf(-2.0f, rc, 1.0f);
}

// ---------------------------------------------------------------------------
// prep: permute W_e into fragment-major g_Wfrag
// layout: [nt(2)][kt(16)] blocks of 8192 floats:
//   [wn(4)][ks(4)][j(4)][lane(32)][e(4)]
//   e: {ni=2j,b0},{2j,b1},{2j+1,b0},{2j+1,b1}
//   n = nt*256 + wn*64 + (2j + e>>1)*8 + (lane>>2)
//   k = kt*32 + ks*8 + (lane&3) + 4*(e&1)
// ---------------------------------------------------------------------------
__global__ void __launch_bounds__(256) prep_kernel(const float* __restrict__ W_attn)
{
    int idx   = blockIdx.x * 256 + threadIdx.x;     // 0..262143
    int block = idx >> 13;
    int w     = idx & 8191;
    int wn    = w >> 11;
    int ks    = (w >> 9) & 3;
    int j     = (w >> 7) & 3;
    int lane  = (w >> 2) & 31;
    int e     = w & 3;
    int nt = block >> 4, kt = block & 15;
    int n = nt * 256 + wn * 64 + (2 * j + (e >> 1)) * 8 + (lane >> 2);
    int k = kt * 32 + ks * 8 + (lane & 3) + 4 * (e & 1);
    g_Wfrag[idx] = W_attn[(size_t)(DHDIM + k) * HDIM + n];
}

// ---------------------------------------------------------------------------
// hp: split-K h_part (proven in R3)
// ---------------------------------------------------------------------------
__global__ void __launch_bounds__(256) hp1_kernel(
    const float* __restrict__ hidden, const float* __restrict__ W_attn)
{
    int b = blockIdx.x, ks = blockIdx.y;
    int d = blockIdx.z * 256 + threadIdx.x;
    const float* hrow = hidden + (size_t)b * DHDIM + ks * 128;
    const float* wp = W_attn + (size_t)(ks * 128) * HDIM + d;
    float acc = 0.f;
#pragma unroll 8
    for (int k = 0; k < 128; ++k)
        acc += __ldg(hrow + k) * wp[(size_t)k * HDIM];
    g_hp_part[((size_t)ks * BDIM + b) * HDIM + d] = acc;
}

__global__ void __launch_bounds__(256) hp2_kernel(const float* __restrict__ b_attn)
{
    int i = blockIdx.x * 256 + threadIdx.x;
    float s = b_attn[i & (HDIM - 1)];
#pragma unroll
    for (int ks = 0; ks < 16; ++ks)
        s += g_hp_part[(size_t)ks * (BDIM * HDIM) + i];
    g_hp[i] = s;
}

// ---------------------------------------------------------------------------
// main: tf32 mma.sync, 64x64 warp tiles, cp.async 3-buffer pipeline,
// fused FFMA tanh + v-dot epilogue.  grid 512 CTAs x 256 threads.
// ---------------------------------------------------------------------------
__device__ __forceinline__ void prefetch_stage(
    float* __restrict__ dst, const float* __restrict__ enc,
    const float* __restrict__ wf, int m0, int nt, int kt, int tid)
{
    // A: 128x32, swizzled: chunk (row, c4) -> row*32 + ((c4+row)&7)*4
    const float* asrc = enc + (size_t)m0 * HDIM + kt * BK;
#pragma unroll
    for (int q = 0; q < 4; ++q) {
        int idx = q * 256 + tid;
        int row = idx >> 3;
        int c4  = idx & 7;
        cp16(dst + row * 32 + ((c4 + row) & 7) * 4,
             asrc + (size_t)row * HDIM + c4 * 4);
    }
    // B: 8192 floats, flat contiguous from g_Wfrag
    const float* bsrc = wf + (size_t)(nt * 16 + kt) * B_FLOATS;
    float* bdst = dst + A_FLOATS;
#pragma unroll
    for (int q = 0; q < 8; ++q) {
        int idx = q * 256 + tid;
        cp16(bdst + idx * 4, bsrc + idx * 4);
    }
}

__global__ void __launch_bounds__(256) main_kernel(
    const float* __restrict__ enc,
    const float* __restrict__ v,
    float* __restrict__ out)
{
    extern __shared__ float smem[];
    float* vs     = smem;                        // [512]
    float* red    = smem + VS_FLOATS;            // [4][128]
    float* stages = red + RED_FLOATS;            // 3 x 12288

    int tid  = threadIdx.x;
    int lane = tid & 31;
    int warp = tid >> 5;
    int wm   = warp >> 2;       // 0..1
    int wn   = warp & 3;        // 0..3
    int grp  = lane >> 2;       // 0..7
    int tig  = lane & 3;        // 0..3
    int m0   = blockIdx.x * BM;

    for (int i = tid; i < HDIM; i += 256) vs[i] = v[i];

    float lp[8];
#pragma unroll
    for (int j = 0; j < 8; ++j) lp[j] = 0.f;

    for (int nt = 0; nt < NT; ++nt) {
        prefetch_stage(stages, enc, g_Wfrag, m0, nt, 0, tid);
        cp_commit();
        prefetch_stage(stages + STAGE_FLOATS, enc, g_Wfrag, m0, nt, 1, tid);
        cp_commit();

        float c[4][8][4];
#pragma unroll
        for (int mi = 0; mi < 4; ++mi)
#pragma unroll
            for (int ni = 0; ni < 8; ++ni)
#pragma unroll
                for (int q = 0; q < 4; ++q) c[mi][ni][q] = 0.f;

        int sidx = 0;
        for (int kt = 0; kt < KT; ++kt) {
            if (kt == KT - 1) cp_wait<0>(); else cp_wait<1>();
            __syncthreads();
            if (kt + 2 < KT) {
                int ps = sidx + 2; if (ps >= 3) ps -= 3;
                prefetch_stage(stages + ps * STAGE_FLOATS, enc, g_Wfrag, m0, nt, kt + 2, tid);
                cp_commit();
            }

            const float* As = stages + sidx * STAGE_FLOATS;
            const float* Bs = As + A_FLOATS;

#pragma unroll
            for (int ks = 0; ks < 4; ++ks) {
                uint32_t a[4][4];
#pragma unroll
                for (int mi = 0; mi < 4; ++mi) {
                    int r0 = wm * 64 + mi * 16 + grp;
                    int r1 = r0 + 8;
                    a[mi][0] = __float_as_uint(As[r0 * 32 + ((ks * 2 + r0) & 7) * 4 + tig]);
                    a[mi][1] = __float_as_uint(As[r1 * 32 + ((ks * 2 + r1) & 7) * 4 + tig]);
                    a[mi][2] = __float_as_uint(As[r0 * 32 + ((ks * 2 + 1 + r0) & 7) * 4 + tig]);
                    a[mi][3] = __float_as_uint(As[r1 * 32 + ((ks * 2 + 1 + r1) & 7) * 4 + tig]);
                }
#pragma unroll
                for (int j = 0; j < 4; ++j) {
                    float4 bb = *reinterpret_cast<const float4*>(
                        Bs + wn * 2048 + ks * 512 + j * 128 + lane * 4);
                    uint32_t b0 = __float_as_uint(bb.x), b1 = __float_as_uint(bb.y);
                    uint32_t b2 = __float_as_uint(bb.z), b3 = __float_as_uint(bb.w);
#pragma unroll
                    for (int mi = 0; mi < 4; ++mi) {
                        mma8(c[mi][2 * j],     a[mi][0], a[mi][1], a[mi][2], a[mi][3], b0, b1);
                        mma8(c[mi][2 * j + 1], a[mi][0], a[mi][1], a[mi][2], a[mi][3], b2, b3);
                    }
                }
            }
            if (++sidx == 3) sidx = 0;
        }

        // ---- epilogue for this nt half ----
        __syncthreads();                       // everyone done with stage reads
        float* hps = stages;                   // overlay [32][264]
        for (int i = tid; i < 32 * 256; i += 256)
            hps[(i >> 8) * HPS_STRIDE + (i & 255)] =
                g_hp[(i >> 8) * HDIM + nt * BN + (i & 255)];
        __syncthreads();

#pragma unroll
        for (int mi = 0; mi < 4; ++mi) {
            int r0 = wm * 64 + mi * 16 + grp;
            int b0 = r0 & 31;
            int b1 = (r0 + 8) & 31;
#pragma unroll
            for (int ni = 0; ni < 8; ++ni) {
                int n0 = wn * 64 + ni * 8 + 2 * tig;
                float v0 = vs[nt * BN + n0], v1 = vs[nt * BN + n0 + 1];
                float t00 = tanh_fma(c[mi][ni][0] + hps[b0 * HPS_STRIDE + n0]);
                float t01 = tanh_fma(c[mi][ni][1] + hps[b0 * HPS_STRIDE + n0 + 1]);
                float t10 = tanh_fma(c[mi][ni][2] + hps[b1 * HPS_STRIDE + n0]);
                float t11 = tanh_fma(c[mi][ni][3] + hps[b1 * HPS_STRIDE + n0 + 1]);
                lp[mi * 2 + 0] += t00 * v0 + t01 * v1;
                lp[mi * 2 + 1] += t10 * v0 + t11 * v1;
            }
        }
        __syncthreads();                       // hps dead before next nt prefetch
    }

    // ---- reduce: tig lanes -> red[wn][row] -> sum over wn ----
#pragma unroll
    for (int j = 0; j < 8; ++j) {
        lp[j] += __shfl_xor_sync(0xffffffffu, lp[j], 1);
        lp[j] += __shfl_xor_sync(0xffffffffu, lp[j], 2);
    }
    if (tig == 0) {
#pragma unroll
        for (int j = 0; j < 8; ++j) {
            int r = wm * 64 + (j >> 1) * 16 + grp + (j & 1) * 8;
            red[wn * 128 + r] = lp[j];
        }
    }
    __syncthreads();
    if (tid < 128) {
        float lg = red[tid] + red[128 + tid] + red[256 + tid] + red[384 + tid];
        int f = m0 + tid;
        out[(f & 31) * SDIM + (f >> 5)] = lg;
    }
}

// ---------------------------------------------------------------------------
// softmax over s per batch row, in place
// ---------------------------------------------------------------------------
__global__ void __launch_bounds__(256) softmax_kernel(float* __restrict__ out)
{
    __shared__ float sred[8];
    int b = blockIdx.x, tid = threadIdx.x;
    float* row = out + (size_t)b * SDIM;

    float vals[8];
    float mx = -3.4e38f;
#pragma unroll
    for (int i = 0; i < 8; ++i) {
        vals[i] = row[tid + i * 256];
        mx = fmaxf(mx, vals[i]);
    }
#pragma unroll
    for (int o = 16; o > 0; o >>= 1) mx = fmaxf(mx, __shfl_xor_sync(0xffffffffu, mx, o));
    if ((tid & 31) == 0) sred[tid >> 5] = mx;
    __syncthreads();
    mx = sred[0];
#pragma unroll
    for (int w = 1; w < 8; ++w) mx = fmaxf(mx, sred[w]);
    __syncthreads();

    float sum = 0.f;
#pragma unroll
    for (int i = 0; i < 8; ++i) { vals[i] = __expf(vals[i] - mx); sum += vals[i]; }
#pragma unroll
    for (int o = 16; o > 0; o >>= 1) sum += __shfl_xor_sync(0xffffffffu, sum, o);
    if ((tid & 31) == 0) sred[tid >> 5] = sum;
    __syncthreads();
    float tot = 0.f;
#pragma unroll
    for (int w = 0; w < 8; ++w) tot += sred[w];
    float inv = 1.0f / tot;
#pragma unroll
    for (int i = 0; i < 8; ++i) row[tid + i * 256] = vals[i] * inv;
}

// ---------------------------------------------------------------------------
extern "C" void kernel_launch(void* const* d_in, const int* in_sizes, int n_in,
                              void* d_out, int out_size)
{
    const float* hidden = (const float*)d_in[0];
    const float* enc    = (const float*)d_in[1];
    const float* W_attn = (const float*)d_in[2];
    const float* b_attn = (const float*)d_in[3];
    const float* v      = (const float*)d_in[4];
    float* out = (float*)d_out;
    (void)in_sizes; (void)n_in; (void)out_size;

    static cudaError_t attr_rc = cudaFuncSetAttribute(
        main_kernel, cudaFuncAttributeMaxDynamicSharedMemorySize, SMEM_BYTES);
    (void)attr_rc;

    prep_kernel<<<1024, 256>>>(W_attn);
    hp1_kernel<<<dim3(32, 16, 2), 256>>>(hidden, W_attn);
    hp2_kernel<<<64, 256>>>(b_attn);
    main_kernel<<<MTOK / BM, 256, SMEM_BYTES>>>(enc, v, out);
    softmax_kernel<<<BDIM, 256>>>(out);
}

// round 6
// speedup vs baseline: 2.6631x; 1.3349x over previous
#include <cuda_runtime.h>
#include <cuda_fp16.h>
#include <cstdint>

#define BDIM   32
#define SDIM   2048
#define HDIM   512
#define DHDIM  2048
#define MTOK   65536

#define BM 128
#define BN 256          // per nt half
#define NT 2
#define BK 32
#define KT 16

// smem layout
#define A_ROW_H    40                    // halves per A row (80B, conflict-free ldmatrix)
#define A_STAGE_H  (128 * A_ROW_H)       // 5120 halves = 10240 B
#define B_STAGE_H  8192                  // halves = 16384 B
#define STAGE_H    (A_STAGE_H + B_STAGE_H)   // 13312 halves
#define STAGE_B    (STAGE_H * 2)             // 26624 B
#define SMEM_BYTES (4096 + 3 * STAGE_B)      // 83968
#define HPS_STRIDE 264

__device__ float  g_hp[BDIM * HDIM];
__device__ float  g_hp_part[16 * BDIM * HDIM];
__device__ __half g_enc_h[(size_t)MTOK * HDIM];     // fp16 encoder copy
__device__ __half g_WfragH[HDIM * HDIM];            // fragment-major fp16 W_e

// ---------------------------------------------------------------------------
// helpers
// ---------------------------------------------------------------------------
__device__ __forceinline__ void cp16(void* dst_smem, const void* src) {
    uint32_t d = (uint32_t)__cvta_generic_to_shared(dst_smem);
    asm volatile("cp.async.ca.shared.global [%0], [%1], 16;\n" :: "r"(d), "l"(src));
}
__device__ __forceinline__ void cp_commit() {
    asm volatile("cp.async.commit_group;\n");
}
template<int N>
__device__ __forceinline__ void cp_wait() {
    asm volatile("cp.async.wait_group %0;\n" :: "n"(N));
}

__device__ __forceinline__ void ldmatrix4(uint32_t* a, uint32_t addr) {
    asm volatile("ldmatrix.sync.aligned.m8n8.x4.shared.b16 {%0,%1,%2,%3}, [%4];"
                 : "=r"(a[0]), "=r"(a[1]), "=r"(a[2]), "=r"(a[3]) : "r"(addr));
}

__device__ __forceinline__ void mma16(float* c, const uint32_t* a,
                                      uint32_t b0, uint32_t b1) {
    asm volatile(
        "mma.sync.aligned.m16n8k16.row.col.f32.f16.f16.f32 "
        "{%0,%1,%2,%3}, {%4,%5,%6,%7}, {%8,%9}, {%0,%1,%2,%3};"
        : "+f"(c[0]), "+f"(c[1]), "+f"(c[2]), "+f"(c[3])
        : "r"(a[0]), "r"(a[1]), "r"(a[2]), "r"(a[3]), "r"(b0), "r"(b1));
}

// FFMA-only tanh (no MUFU): abs err ~1e-5
__device__ __forceinline__ float tanh_fma(float x) {
    x = fminf(fmaxf(x, -15.0f), 15.0f);
    const float L2E2 = 2.885390081777927f;
    float tm = fmaf(x, L2E2, 12582912.0f);
    int   ei = __float_as_int(tm) - 0x4B400000;
    float r  = fmaf(x, L2E2, 12582912.0f - tm);
    float p  = 1.54035303934e-4f;
    p = fmaf(p, r, 1.33335581464e-3f);
    p = fmaf(p, r, 9.61812910763e-3f);
    p = fmaf(p, r, 5.55041086648e-2f);
    p = fmaf(p, r, 2.40226506959e-1f);
    p = fmaf(p, r, 6.93147180560e-1f);
    p = fmaf(p, r, 1.0f);
    float y  = p * __int_as_float((ei + 127) << 23);
    float e1 = y + 1.0f;
    float rc = __int_as_float(0x7EF127EAu - (uint32_t)__float_as_int(e1));
    rc = rc * fmaf(-e1, rc, 2.0f);
    rc = rc * fmaf(-e1, rc, 2.0f);
    rc = rc * fmaf(-e1, rc, 2.0f);
    return fmaf(-2.0f, rc, 1.0f);
}

// ---------------------------------------------------------------------------
// conv: enc f32 -> fp16  (each thread 8 elems)
// ---------------------------------------------------------------------------
__global__ void __launch_bounds__(256) conv_kernel(const float* __restrict__ enc)
{
    size_t i = ((size_t)blockIdx.x * 256 + threadIdx.x) * 8;
    float4 x = *reinterpret_cast<const float4*>(enc + i);
    float4 y = *reinterpret_cast<const float4*>(enc + i + 4);
    __half2 h0 = __floats2half2_rn(x.x, x.y);
    __half2 h1 = __floats2half2_rn(x.z, x.w);
    __half2 h2 = __floats2half2_rn(y.x, y.y);
    __half2 h3 = __floats2half2_rn(y.z, y.w);
    uint4 o;
    o.x = *reinterpret_cast<uint32_t*>(&h0);
    o.y = *reinterpret_cast<uint32_t*>(&h1);
    o.z = *reinterpret_cast<uint32_t*>(&h2);
    o.w = *reinterpret_cast<uint32_t*>(&h3);
    *reinterpret_cast<uint4*>(g_enc_h + i) = o;
}

// ---------------------------------------------------------------------------
// wprep: W_e -> fp16 fragment-major
// layout: [nt2][kt16] blocks of 8192 halves: [wn4][ks2][jj4][lane32][h8]
//   ni = 2*jj + (h>>2); hh = h&3
//   k = kt*32 + ks*16 + 2*tig + (hh&1) + ((hh>>1)&1)*8
//   n = nt*256 + wn*64 + ni*8 + grp
// ---------------------------------------------------------------------------
__global__ void __launch_bounds__(256) wprep_kernel(const float* __restrict__ W_attn)
{
    int idx  = blockIdx.x * 256 + threadIdx.x;      // 0..262143
    int h    = idx & 7;
    int lane = (idx >> 3) & 31;
    int jj   = (idx >> 8) & 3;
    int ks   = (idx >> 10) & 1;
    int wn   = (idx >> 11) & 3;
    int kt   = (idx >> 13) & 15;
    int nt   = idx >> 17;
    int tig = lane & 3, grp = lane >> 2;
    int ni = 2 * jj + (h >> 2);
    int hh = h & 3;
    int k = kt * 32 + ks * 16 + 2 * tig + (hh & 1) + ((hh >> 1) & 1) * 8;
    int n = nt * 256 + wn * 64 + ni * 8 + grp;
    g_WfragH[idx] = __float2half_rn(W_attn[(size_t)(DHDIM + k) * HDIM + n]);
}

// ---------------------------------------------------------------------------
// hp: split-K h_part (proven)
// ---------------------------------------------------------------------------
__global__ void __launch_bounds__(256) hp1_kernel(
    const float* __restrict__ hidden, const float* __restrict__ W_attn)
{
    int b = blockIdx.x, ks = blockIdx.y;
    int d = blockIdx.z * 256 + threadIdx.x;
    const float* hrow = hidden + (size_t)b * DHDIM + ks * 128;
    const float* wp = W_attn + (size_t)(ks * 128) * HDIM + d;
    float acc = 0.f;
#pragma unroll 8
    for (int k = 0; k < 128; ++k)
        acc += __ldg(hrow + k) * wp[(size_t)k * HDIM];
    g_hp_part[((size_t)ks * BDIM + b) * HDIM + d] = acc;
}

__global__ void __launch_bounds__(256) hp2_kernel(const float* __restrict__ b_attn)
{
    int i = blockIdx.x * 256 + threadIdx.x;
    float s = b_attn[i & (HDIM - 1)];
#pragma unroll
    for (int ks = 0; ks < 16; ++ks)
        s += g_hp_part[(size_t)ks * (BDIM * HDIM) + i];
    g_hp[i] = s;
}

// ---------------------------------------------------------------------------
// main: fp16 mma.sync m16n8k16, 64x64 warp tiles, ldmatrix A, cp.async 3-buf
// grid 512 CTAs x 256 threads
// ---------------------------------------------------------------------------
__device__ __forceinline__ void prefetch_stage(
    __half* __restrict__ dst, int m0, int nt, int kt, int tid)
{
    // A: 128 rows x 32 halves -> rows padded to 40 halves
    const __half* asrc = g_enc_h + (size_t)m0 * HDIM + kt * BK;
#pragma unroll
    for (int q = 0; q < 2; ++q) {
        int idx = q * 256 + tid;          // 0..511
        int row = idx >> 2;
        int c   = idx & 3;                // 8-half chunk
        cp16(dst + row * A_ROW_H + c * 8, asrc + (size_t)row * HDIM + c * 8);
    }
    // B: 8192 halves flat
    const __half* bsrc = g_WfragH + (size_t)(nt * 16 + kt) * B_STAGE_H;
    __half* bdst = dst + A_STAGE_H;
#pragma unroll
    for (int q = 0; q < 4; ++q) {
        int idx = q * 256 + tid;
        cp16(bdst + idx * 8, bsrc + idx * 8);
    }
}

__global__ void __launch_bounds__(256) main_kernel(
    const float* __restrict__ v,
    float* __restrict__ out)
{
    extern __shared__ char smem_raw[];
    float*  vs     = (float*)smem_raw;                 // [512]
    float*  red    = (float*)(smem_raw + 2048);        // [4][128]
    __half* stages = (__half*)(smem_raw + 4096);       // 3 x STAGE_H

    int tid  = threadIdx.x;
    int lane = tid & 31;
    int warp = tid >> 5;
    int wm   = warp >> 2;       // 0..1
    int wn   = warp & 3;        // 0..3
    int grp  = lane >> 2;       // 0..7
    int tig  = lane & 3;        // 0..3
    int m0   = blockIdx.x * BM;

    // ldmatrix row/col offsets for this lane
    int lrow = lane & 15;
    int lcol = (lane >> 4) << 3;

    for (int i = tid; i < HDIM; i += 256) vs[i] = v[i];

    float lp[8];
#pragma unroll
    for (int j = 0; j < 8; ++j) lp[j] = 0.f;

    for (int nt = 0; nt < NT; ++nt) {
        prefetch_stage(stages, m0, nt, 0, tid);
        cp_commit();
        prefetch_stage(stages + STAGE_H, m0, nt, 1, tid);
        cp_commit();

        float c[4][8][4];
#pragma unroll
        for (int mi = 0; mi < 4; ++mi)
#pragma unroll
            for (int ni = 0; ni < 8; ++ni)
#pragma unroll
                for (int q = 0; q < 4; ++q) c[mi][ni][q] = 0.f;

        int sidx = 0;
        for (int kt = 0; kt < KT; ++kt) {
            if (kt == KT - 1) cp_wait<0>(); else cp_wait<1>();
            __syncthreads();
            if (kt + 2 < KT) {
                int ps = sidx + 2; if (ps >= 3) ps -= 3;
                prefetch_stage(stages + ps * STAGE_H, m0, nt, kt + 2, tid);
                cp_commit();
            }

            const __half* As = stages + sidx * STAGE_H;
            const __half* Bs = As + A_STAGE_H;
            uint32_t abase = (uint32_t)__cvta_generic_to_shared(As);

#pragma unroll
            for (int ks = 0; ks < 2; ++ks) {
                uint32_t a[4][4];
#pragma unroll
                for (int mi = 0; mi < 4; ++mi) {
                    int row = wm * 64 + mi * 16 + lrow;
                    int col = ks * 16 + lcol;
                    ldmatrix4(a[mi], abase + (uint32_t)(row * A_ROW_H + col) * 2);
                }
#pragma unroll
                for (int jj = 0; jj < 4; ++jj) {
                    uint4 bb = reinterpret_cast<const uint4*>(
                        Bs + wn * 2048 + ks * 1024 + jj * 256)[lane];
#pragma unroll
                    for (int mi = 0; mi < 4; ++mi) {
                        mma16(c[mi][2 * jj],     a[mi], bb.x, bb.y);
                        mma16(c[mi][2 * jj + 1], a[mi], bb.z, bb.w);
                    }
                }
            }
            if (++sidx == 3) sidx = 0;
        }

        // ---- epilogue for this nt half ----
        __syncthreads();
        float* hps = (float*)stages;       // overlay [32][264]
        for (int i = tid; i < 32 * 256; i += 256)
            hps[(i >> 8) * HPS_STRIDE + (i & 255)] =
                g_hp[(i >> 8) * HDIM + nt * BN + (i & 255)];
        __syncthreads();

#pragma unroll
        for (int mi = 0; mi < 4; ++mi) {
            int r0 = wm * 64 + mi * 16 + grp;
            int b0 = r0 & 31;
            int b1 = (r0 + 8) & 31;
#pragma unroll
            for (int ni = 0; ni < 8; ++ni) {
                int n0 = wn * 64 + ni * 8 + 2 * tig;
                float v0 = vs[nt * BN + n0], v1 = vs[nt * BN + n0 + 1];
                float t00 = tanh_fma(c[mi][ni][0] + hps[b0 * HPS_STRIDE + n0]);
                float t01 = tanh_fma(c[mi][ni][1] + hps[b0 * HPS_STRIDE + n0 + 1]);
                float t10 = tanh_fma(c[mi][ni][2] + hps[b1 * HPS_STRIDE + n0]);
                float t11 = tanh_fma(c[mi][ni][3] + hps[b1 * HPS_STRIDE + n0 + 1]);
                lp[mi * 2 + 0] += t00 * v0 + t01 * v1;
                lp[mi * 2 + 1] += t10 * v0 + t11 * v1;
            }
        }
        __syncthreads();                   // hps dead before next nt prefetch
    }

    // ---- reduce ----
#pragma unroll
    for (int j = 0; j < 8; ++j) {
        lp[j] += __shfl_xor_sync(0xffffffffu, lp[j], 1);
        lp[j] += __shfl_xor_sync(0xffffffffu, lp[j], 2);
    }
    if (tig == 0) {
#pragma unroll
        for (int j = 0; j < 8; ++j) {
            int r = wm * 64 + (j >> 1) * 16 + grp + (j & 1) * 8;
            red[wn * 128 + r] = lp[j];
        }
    }
    __syncthreads();
    if (tid < 128) {
        float lg = red[tid] + red[128 + tid] + red[256 + tid] + red[384 + tid];
        int f = m0 + tid;
        out[(f & 31) * SDIM + (f >> 5)] = lg;
    }
}

// ---------------------------------------------------------------------------
// softmax over s per batch row, in place
// ---------------------------------------------------------------------------
__global__ void __launch_bounds__(256) softmax_kernel(float* __restrict__ out)
{
    __shared__ float sred[8];
    int b = blockIdx.x, tid = threadIdx.x;
    float* row = out + (size_t)b * SDIM;

    float vals[8];
    float mx = -3.4e38f;
#pragma unroll
    for (int i = 0; i < 8; ++i) {
        vals[i] = row[tid + i * 256];
        mx = fmaxf(mx, vals[i]);
    }
#pragma unroll
    for (int o = 16; o > 0; o >>= 1) mx = fmaxf(mx, __shfl_xor_sync(0xffffffffu, mx, o));
    if ((tid & 31) == 0) sred[tid >> 5] = mx;
    __syncthreads();
    mx = sred[0];
#pragma unroll
    for (int w = 1; w < 8; ++w) mx = fmaxf(mx, sred[w]);
    __syncthreads();

    float sum = 0.f;
#pragma unroll
    for (int i = 0; i < 8; ++i) { vals[i] = __expf(vals[i] - mx); sum += vals[i]; }
#pragma unroll
    for (int o = 16; o > 0; o >>= 1) sum += __shfl_xor_sync(0xffffffffu, sum, o);
    if ((tid & 31) == 0) sred[tid >> 5] = sum;
    __syncthreads();
    float tot = 0.f;
#pragma unroll
    for (int w = 0; w < 8; ++w) tot += sred[w];
    float inv = 1.0f / tot;
#pragma unroll
    for (int i = 0; i < 8; ++i) row[tid + i * 256] = vals[i] * inv;
}

// ---------------------------------------------------------------------------
extern "C" void kernel_launch(void* const* d_in, const int* in_sizes, int n_in,
                              void* d_out, int out_size)
{
    const float* hidden = (const float*)d_in[0];
    const float* enc    = (const float*)d_in[1];
    const float* W_attn = (const float*)d_in[2];
    const float* b_attn = (const float*)d_in[3];
    const float* v      = (const float*)d_in[4];
    float* out = (float*)d_out;
    (void)in_sizes; (void)n_in; (void)out_size;

    static cudaError_t attr_rc = cudaFuncSetAttribute(
        main_kernel, cudaFuncAttributeMaxDynamicSharedMemorySize, SMEM_BYTES);
    (void)attr_rc;

    conv_kernel<<<16384, 256>>>(enc);
    wprep_kernel<<<1024, 256>>>(W_attn);
    hp1_kernel<<<dim3(32, 16, 2), 256>>>(hidden, W_attn);
    hp2_kernel<<<64, 256>>>(b_attn);
    main_kernel<<<MTOK / BM, 256, SMEM_BYTES>>>(v, out);
    softmax_kernel<<<BDIM, 256>>>(out);
}